// round 9
// baseline (speedup 1.0000x reference)
#include <cuda_runtime.h>
#include <cuda_bf16.h>
#include <cstdint>

// ChannelPolyLayer: out[b,o,x,y] = sum_c coeffs[b,o,c] * prod_v img[b,v,x,y]^powers[c,v]
// DEGREE=3, NUM_VARS=3, NUM_OUT=3, NUM_COEFFS=20, BATCH=16, H=W=512.
//
// Monomial order from _generate_powers(3,3):
//  0:1  1:v0  2:v1  3:v2  4:v0^2  5:v0v1  6:v0v2  7:v1^2  8:v1v2  9:v2^2
// 10:v0^3 11:v0^2v1 12:v0^2v2 13:v0v1^2 14:v0v1v2 15:v0v2^2
// 16:v1^3 17:v1^2v2 18:v1v2^2 19:v2^3
//
// Nested Horner, packed fma.rn.f32x2 (19 per output per pixel-pair).
// R9: cp.async.cg 4-stage smem pipeline. Loads are decoupled from registers
// (the R4/R6/R8 ceiling): every thread keeps ~9x16B continuously in flight,
// independent of compute phase. Thread t consumes only bytes thread t copied
// -> no __syncthreads in the pipeline; commit_group/wait_group only.
// Smem 48KB/CTA -> 4 CTAs/SM; no reg cap (R5 lesson).

#define HW_PIX (512 * 512)
#define PLANE4 (HW_PIX / 4)       // 65536 float4s per channel plane
#define NBATCH 16
#define NCOEF  20
#define TPB    256
#define CTAS_X 32
#define CHUNK  (PLANE4 / CTAS_X)  // 2048 float4s per CTA
#define TILES  (CHUNK / TPB)      // 8 tiles per CTA
#define STAGES 4

typedef unsigned long long ull;

__device__ __forceinline__ ull ffma2(ull a, ull b, ull c) {
    ull d;
    asm("fma.rn.f32x2 %0, %1, %2, %3;" : "=l"(d) : "l"(a), "l"(b), "l"(c));
    return d;
}

// Horner over a packed pair of pixels. c[] are {coeff,coeff} splat pairs.
__device__ __forceinline__ ull horner2(ull v0, ull v1, ull v2,
                                       const ull* __restrict__ c) {
    ull pA = ffma2(c[16], v1, c[7]);
    pA = ffma2(v1, pA, c[2]);
    pA = ffma2(v1, pA, c[0]);
    ull pB = ffma2(c[17], v1, c[8]);
    pB = ffma2(v1, pB, c[3]);
    ull pC = ffma2(c[18], v1, c[9]);
    ull C0 = ffma2(c[19], v2, pC);
    C0 = ffma2(C0, v2, pB);
    C0 = ffma2(C0, v2, pA);
    ull qA = ffma2(c[13], v1, c[5]);
    qA = ffma2(v1, qA, c[1]);
    ull qB = ffma2(c[14], v1, c[6]);
    ull C1 = ffma2(c[15], v2, qB);
    C1 = ffma2(C1, v2, qA);
    ull C2 = ffma2(c[11], v1, c[4]);
    C2 = ffma2(c[12], v2, C2);
    ull r = ffma2(c[10], v0, C2);
    r = ffma2(r, v0, C1);
    r = ffma2(r, v0, C0);
    return r;
}

__device__ __forceinline__ void cpa16(uint32_t dst_smem, const void* src) {
    asm volatile("cp.async.cg.shared.global [%0], [%1], 16;"
                 :: "r"(dst_smem), "l"(src));
}
#define CP_COMMIT() asm volatile("cp.async.commit_group;")
// Wait until at most N groups are still pending.
#define CP_WAIT(N)  asm volatile("cp.async.wait_group %0;" :: "n"(N))

__global__ void channel_poly_kernel(
    const float* __restrict__ img,     // (B, 3, H, W)
    const float* __restrict__ coeffs,  // (B, 3, 20)
    float* __restrict__ out)           // (B, 3, H, W)
{
    __shared__ ulonglong2 buf[STAGES][3][TPB];   // 48 KB staging
    __shared__ ull sc2[3 * NCOEF];               // this batch's 60 splat pairs

    const int b = blockIdx.y;
    const int t = threadIdx.x;
    if (t < 3 * NCOEF) {
        ull u = (ull)__float_as_uint(coeffs[b * (3 * NCOEF) + t]);
        sc2[t] = u | (u << 32);        // splat {c, c}
    }
    __syncthreads();                   // coeffs only; pipeline needs no barriers

    const int i0 = blockIdx.x * CHUNK;
    const ulonglong2* __restrict__ in =
        reinterpret_cast<const ulonglong2*>(img + (size_t)b * 3 * HW_PIX);
    ulonglong2* __restrict__ op =
        reinterpret_cast<ulonglong2*>(out + (size_t)b * 3 * HW_PIX);

    // Smem addresses for this thread's 3 slots per stage.
    uint32_t sbase[STAGES];
#pragma unroll
    for (int s = 0; s < STAGES; s++)
        sbase[s] = (uint32_t)__cvta_generic_to_shared(&buf[s][0][t]);
    const uint32_t chstride = TPB * sizeof(ulonglong2);   // 4096 B between channels

    // Prologue: issue STAGES-1 tiles.
#pragma unroll
    for (int s = 0; s < STAGES - 1; s++) {
        const int idx = i0 + s * TPB + t;
        cpa16(sbase[s],                in + idx);
        cpa16(sbase[s] + chstride,     in + idx + PLANE4);
        cpa16(sbase[s] + 2 * chstride, in + idx + 2 * PLANE4);
        CP_COMMIT();
    }

#pragma unroll 1
    for (int tile = 0; tile < TILES; tile++) {
        // Issue tile+STAGES-1 (or an empty group to keep wait accounting uniform).
        const int tnext = tile + STAGES - 1;
        if (tnext < TILES) {
            const int slot = tnext & (STAGES - 1);
            const int idx = i0 + tnext * TPB + t;
            cpa16(sbase[slot],                in + idx);
            cpa16(sbase[slot] + chstride,     in + idx + PLANE4);
            cpa16(sbase[slot] + 2 * chstride, in + idx + 2 * PLANE4);
        }
        CP_COMMIT();
        CP_WAIT(STAGES - 1);           // tile's group is complete

        const int slot = tile & (STAGES - 1);
        const ulonglong2 x0 = buf[slot][0][t];
        const ulonglong2 x1 = buf[slot][1][t];
        const ulonglong2 x2 = buf[slot][2][t];

        const int oi = i0 + tile * TPB + t;
#pragma unroll 1
        for (int oc = 0; oc < 3; oc++) {
            const ull* __restrict__ c = sc2 + oc * NCOEF;
            ulonglong2 r;
            r.x = horner2(x0.x, x1.x, x2.x, c);
            r.y = horner2(x0.y, x1.y, x2.y, c);
            op[oi + oc * PLANE4] = r;
        }
    }
}

extern "C" void kernel_launch(void* const* d_in, const int* in_sizes, int n_in,
                              void* d_out, int out_size) {
    const float* img = (const float*)d_in[0];     // (16,3,512,512)
    const float* coeffs = (const float*)d_in[1];  // (16,3,20)
    float* out = (float*)d_out;

    dim3 grid(CTAS_X, NBATCH, 1);                 // 32 x 16 = 512 CTAs
    channel_poly_kernel<<<grid, TPB>>>(img, coeffs, out);
}

// round 10
// speedup vs baseline: 1.2165x; 1.2165x over previous
#include <cuda_runtime.h>
#include <cuda_bf16.h>

// ChannelPolyLayer: out[b,o,x,y] = sum_c coeffs[b,o,c] * prod_v img[b,v,x,y]^powers[c,v]
// DEGREE=3, NUM_VARS=3, NUM_OUT=3, NUM_COEFFS=20, BATCH=16, H=W=512.
//
// Monomial order from _generate_powers(3,3):
//  0:1  1:v0  2:v1  3:v2  4:v0^2  5:v0v1  6:v0v2  7:v1^2  8:v1v2  9:v2^2
// 10:v0^3 11:v0^2v1 12:v0^2v2 13:v0v1^2 14:v0v1v2 15:v0v2^2
// 16:v1^3 17:v1^2v2 18:v1v2^2 19:v2^3
//
// Nested Horner, packed fma.rn.f32x2 (19 per output per pixel-pair).
// R10 = R6 (continuous register prefetch, MLP=6 sustained — the only
// structure that beat 17us) + R7's batch-per-blockIdx.y (no batch math)
// + 128-thread CTAs at 5 CTAs/SM: warps/SM 13.7 -> 20 at unchanged
// continuous MLP. launch_bounds(128,5) cap=102 regs, ABOVE natural
// demand (~95) so no R5-style operand-pairing squeeze.

#define HW_PIX (512 * 512)
#define PLANE4 (HW_PIX / 4)       // 65536 float4s per channel plane
#define HALF4  (PLANE4 / 2)       // 32768 items; item j covers float4 j, j+HALF4
#define NBATCH 16
#define NCOEF  20
#define TPB    128
#define CTAS_X 46                 // 46*16 = 736 CTAs ~= one wave at 5 CTAs/SM
#define STRIDE (CTAS_X * TPB)     // 5888

typedef unsigned long long ull;

__device__ __forceinline__ ull ffma2(ull a, ull b, ull c) {
    ull d;
    asm("fma.rn.f32x2 %0, %1, %2, %3;" : "=l"(d) : "l"(a), "l"(b), "l"(c));
    return d;
}

// Horner over a packed pair of pixels. c[] are {coeff,coeff} splat pairs.
__device__ __forceinline__ ull horner2(ull v0, ull v1, ull v2,
                                       const ull* __restrict__ c) {
    ull pA = ffma2(c[16], v1, c[7]);
    pA = ffma2(v1, pA, c[2]);
    pA = ffma2(v1, pA, c[0]);
    ull pB = ffma2(c[17], v1, c[8]);
    pB = ffma2(v1, pB, c[3]);
    ull pC = ffma2(c[18], v1, c[9]);
    ull C0 = ffma2(c[19], v2, pC);
    C0 = ffma2(C0, v2, pB);
    C0 = ffma2(C0, v2, pA);
    ull qA = ffma2(c[13], v1, c[5]);
    qA = ffma2(v1, qA, c[1]);
    ull qB = ffma2(c[14], v1, c[6]);
    ull C1 = ffma2(c[15], v2, qB);
    C1 = ffma2(C1, v2, qA);
    ull C2 = ffma2(c[11], v1, c[4]);
    C2 = ffma2(c[12], v2, C2);
    ull r = ffma2(c[10], v0, C2);
    r = ffma2(r, v0, C1);
    r = ffma2(r, v0, C0);
    return r;
}

__global__ __launch_bounds__(TPB, 5) void channel_poly_kernel(
    const float* __restrict__ img,     // (B, 3, H, W)
    const float* __restrict__ coeffs,  // (B, 3, 20)
    float* __restrict__ out)           // (B, 3, H, W)
{
    __shared__ ull sc2[3 * NCOEF];     // this batch's 60 splat pairs
    const int b = blockIdx.y;
    const int t = threadIdx.x;
    if (t < 3 * NCOEF) {
        ull u = (ull)__float_as_uint(coeffs[b * (3 * NCOEF) + t]);
        sc2[t] = u | (u << 32);        // splat {c, c}
    }
    __syncthreads();                   // the only barrier

    const ulonglong2* __restrict__ in =
        reinterpret_cast<const ulonglong2*>(img + (size_t)b * 3 * HW_PIX);
    ulonglong2* __restrict__ op =
        reinterpret_cast<ulonglong2*>(out + (size_t)b * 3 * HW_PIX);

    int i = blockIdx.x * TPB + t;      // < 5888 < HALF4 always

    // Prefetch first item (6 LDG.128).
    ulonglong2 a0 = in[i],         a1 = in[i + PLANE4],
               a2 = in[i + 2 * PLANE4];
    ulonglong2 b0 = in[i + HALF4], b1 = in[i + HALF4 + PLANE4],
               b2 = in[i + HALF4 + 2 * PLANE4];

#pragma unroll 1
    while (i < HALF4) {
        // Issue next item's 6 loads before computing this one
        // (keeps MLP=6 continuously outstanding per thread).
        const int inext = i + STRIDE;
        const int il = (inext < HALF4) ? inext : i;  // safe addr; result unused on tail
        const ulonglong2 na0 = in[il],         na1 = in[il + PLANE4],
                         na2 = in[il + 2 * PLANE4];
        const ulonglong2 nb0 = in[il + HALF4], nb1 = in[il + HALF4 + PLANE4],
                         nb2 = in[il + HALF4 + 2 * PLANE4];

#pragma unroll 1
        for (int oc = 0; oc < 3; oc++) {
            const ull* __restrict__ c = sc2 + oc * NCOEF;
            ulonglong2 ra, rb;
            ra.x = horner2(a0.x, a1.x, a2.x, c);
            ra.y = horner2(a0.y, a1.y, a2.y, c);
            rb.x = horner2(b0.x, b1.x, b2.x, c);
            rb.y = horner2(b0.y, b1.y, b2.y, c);
            op[i + oc * PLANE4] = ra;
            op[i + HALF4 + oc * PLANE4] = rb;
        }

        // Rotate pipeline.
        i = inext;
        a0 = na0; a1 = na1; a2 = na2;
        b0 = nb0; b1 = nb1; b2 = nb2;
    }
}

extern "C" void kernel_launch(void* const* d_in, const int* in_sizes, int n_in,
                              void* d_out, int out_size) {
    const float* img = (const float*)d_in[0];     // (16,3,512,512)
    const float* coeffs = (const float*)d_in[1];  // (16,3,20)
    float* out = (float*)d_out;

    dim3 grid(CTAS_X, NBATCH, 1);                 // 46 x 16 = 736 CTAs
    channel_poly_kernel<<<grid, TPB>>>(img, coeffs, out);
}

// round 11
// speedup vs baseline: 1.2557x; 1.0322x over previous
#include <cuda_runtime.h>
#include <cuda_bf16.h>

// ChannelPolyLayer: out[b,o,x,y] = sum_c coeffs[b,o,c] * prod_v img[b,v,x,y]^powers[c,v]
// DEGREE=3, NUM_VARS=3, NUM_OUT=3, NUM_COEFFS=20, BATCH=16, H=W=512.
//
// Monomial order from _generate_powers(3,3):
//  0:1  1:v0  2:v1  3:v2  4:v0^2  5:v0v1  6:v0v2  7:v1^2  8:v1v2  9:v2^2
// 10:v0^3 11:v0^2v1 12:v0^2v2 13:v0v1^2 14:v0v1v2 15:v0v2^2
// 16:v1^3 17:v1^2v2 18:v1v2^2 19:v2^3
//
// Nested Horner, packed fma.rn.f32x2 (19 per output per pixel-pair).
// R11 = R6's persistent ~one-wave 256-thread shape (best wall) +
// batch-per-blockIdx.y (no batch decode; R6's alu cost removed) +
// st.global.cs evict-first stores: output (write-once) stops thrashing the
// 50MB input out of the 126MB L2, so graph replays see L2-resident input
// and load latency drops from DRAM-mix toward L2-hit. MLP=6 continuous
// register prefetch unchanged.

#define HW_PIX (512 * 512)
#define PLANE4 (HW_PIX / 4)       // 65536 float4s per channel plane
#define HALF4  (PLANE4 / 2)       // 32768 items; item j covers float4 j, j+HALF4
#define NBATCH 16
#define NCOEF  20
#define TPB    256
#define CTAS_X 18                 // 18*16 = 288 CTAs ~= one wave at 2 CTAs/SM
#define STRIDE (CTAS_X * TPB)     // 4608

typedef unsigned long long ull;

__device__ __forceinline__ ull ffma2(ull a, ull b, ull c) {
    ull d;
    asm("fma.rn.f32x2 %0, %1, %2, %3;" : "=l"(d) : "l"(a), "l"(b), "l"(c));
    return d;
}

// Streaming (evict-first) 16B store.
__device__ __forceinline__ void stcs16(ulonglong2* p, ulonglong2 v) {
    asm volatile("st.global.cs.v2.u64 [%0], {%1, %2};"
                 :: "l"(p), "l"(v.x), "l"(v.y) : "memory");
}

// Horner over a packed pair of pixels. c[] are {coeff,coeff} splat pairs.
__device__ __forceinline__ ull horner2(ull v0, ull v1, ull v2,
                                       const ull* __restrict__ c) {
    ull pA = ffma2(c[16], v1, c[7]);
    pA = ffma2(v1, pA, c[2]);
    pA = ffma2(v1, pA, c[0]);
    ull pB = ffma2(c[17], v1, c[8]);
    pB = ffma2(v1, pB, c[3]);
    ull pC = ffma2(c[18], v1, c[9]);
    ull C0 = ffma2(c[19], v2, pC);
    C0 = ffma2(C0, v2, pB);
    C0 = ffma2(C0, v2, pA);
    ull qA = ffma2(c[13], v1, c[5]);
    qA = ffma2(v1, qA, c[1]);
    ull qB = ffma2(c[14], v1, c[6]);
    ull C1 = ffma2(c[15], v2, qB);
    C1 = ffma2(C1, v2, qA);
    ull C2 = ffma2(c[11], v1, c[4]);
    C2 = ffma2(c[12], v2, C2);
    ull r = ffma2(c[10], v0, C2);
    r = ffma2(r, v0, C1);
    r = ffma2(r, v0, C0);
    return r;
}

__global__ __launch_bounds__(TPB, 2) void channel_poly_kernel(
    const float* __restrict__ img,     // (B, 3, H, W)
    const float* __restrict__ coeffs,  // (B, 3, 20)
    float* __restrict__ out)           // (B, 3, H, W)
{
    __shared__ ull sc2[3 * NCOEF];     // this batch's 60 splat pairs
    const int b = blockIdx.y;
    const int t = threadIdx.x;
    if (t < 3 * NCOEF) {
        ull u = (ull)__float_as_uint(coeffs[b * (3 * NCOEF) + t]);
        sc2[t] = u | (u << 32);        // splat {c, c}
    }
    __syncthreads();                   // the only barrier

    const ulonglong2* __restrict__ in =
        reinterpret_cast<const ulonglong2*>(img + (size_t)b * 3 * HW_PIX);
    ulonglong2* __restrict__ op =
        reinterpret_cast<ulonglong2*>(out + (size_t)b * 3 * HW_PIX);

    int i = blockIdx.x * TPB + t;      // < 4608 < HALF4 always

    // Prefetch first item (6 LDG.128).
    ulonglong2 a0 = in[i],         a1 = in[i + PLANE4],
               a2 = in[i + 2 * PLANE4];
    ulonglong2 b0 = in[i + HALF4], b1 = in[i + HALF4 + PLANE4],
               b2 = in[i + HALF4 + 2 * PLANE4];

#pragma unroll 1
    while (i < HALF4) {
        // Issue next item's 6 loads before computing this one
        // (keeps MLP=6 continuously outstanding per thread).
        const int inext = i + STRIDE;
        const int il = (inext < HALF4) ? inext : i;  // safe addr; result unused on tail
        const ulonglong2 na0 = in[il],         na1 = in[il + PLANE4],
                         na2 = in[il + 2 * PLANE4];
        const ulonglong2 nb0 = in[il + HALF4], nb1 = in[il + HALF4 + PLANE4],
                         nb2 = in[il + HALF4 + 2 * PLANE4];

#pragma unroll 1
        for (int oc = 0; oc < 3; oc++) {
            const ull* __restrict__ c = sc2 + oc * NCOEF;
            ulonglong2 ra, rb;
            ra.x = horner2(a0.x, a1.x, a2.x, c);
            ra.y = horner2(a0.y, a1.y, a2.y, c);
            rb.x = horner2(b0.x, b1.x, b2.x, c);
            rb.y = horner2(b0.y, b1.y, b2.y, c);
            stcs16(op + i + oc * PLANE4, ra);
            stcs16(op + i + HALF4 + oc * PLANE4, rb);
        }

        // Rotate pipeline.
        i = inext;
        a0 = na0; a1 = na1; a2 = na2;
        b0 = nb0; b1 = nb1; b2 = nb2;
    }
}

extern "C" void kernel_launch(void* const* d_in, const int* in_sizes, int n_in,
                              void* d_out, int out_size) {
    const float* img = (const float*)d_in[0];     // (16,3,512,512)
    const float* coeffs = (const float*)d_in[1];  // (16,3,20)
    float* out = (float*)d_out;

    dim3 grid(CTAS_X, NBATCH, 1);                 // 18 x 16 = 288 CTAs
    channel_poly_kernel<<<grid, TPB>>>(img, coeffs, out);
}